// round 13
// baseline (speedup 1.0000x reference)
#include <cuda_runtime.h>
#include <math.h>

#define Bn 8
#define Tn 2048
#define Dn 64
#define Fn 128
#define NCH 64      // T-chunks in k3 / partial
#define TC 32       // T per k3 chunk
#define T1 32       // T per k1 CTA

// ---------------- scratch (static device globals: allocation-free) ----------------
__device__ __align__(16) float g_a[Dn];                 // lse(wei) - wei[d]
__device__ __align__(16) float g_dd[Dn];                // ||dic_d||^2
__device__ float g_dT[Fn * Dn];                         // dic transposed [k][d]
__device__ float g_w[(size_t)Bn * Tn * Dn];             // [b][t][d], 4 MB
__device__ float g_psum[Bn * NCH * Dn];                 // per-chunk sum_t w
__device__ float g_partial[(size_t)Bn * NCH * Dn * Fn]; // [b][ch][d][f], 16 MB

typedef unsigned long long u64;
#define PACK2(dst, lo, hi)   asm("mov.b64 %0, {%1, %2};" : "=l"(dst) : "f"(lo), "f"(hi))
#define UNPACK2(lo, hi, src) asm("mov.b64 {%0, %1}, %2;" : "=f"(lo), "=f"(hi) : "l"(src))
#define FFMA2(d_, a_, b_, c_) asm("fma.rn.f32x2 %0, %1, %2, %3;" : "=l"(d_) : "l"(a_), "l"(b_), "l"(c_))

// ======== k0: g_dT transpose, g_dd, g_a (grid 64 CTAs x 128 thr) ========
__global__ void __launch_bounds__(128) k0(const float* __restrict__ dic,
                                          const float* __restrict__ wei) {
    __shared__ float sred[4];
    int d = blockIdx.x;
    int tid = threadIdx.x;
    int lane = tid & 31, w = tid >> 5;

    float v = dic[(size_t)d * Fn + tid];
    g_dT[(size_t)tid * Dn + d] = v;       // [k][d]

    float p = v * v;                      // block-reduce ||dic_d||^2
    #pragma unroll
    for (int o = 16; o; o >>= 1) p += __shfl_xor_sync(0xffffffffu, p, o);
    if (lane == 0) sred[w] = p;
    __syncthreads();
    if (tid == 0) g_dd[d] = sred[0] + sred[1] + sred[2] + sred[3];

    if (w == 0) {                         // warp 0: a[d] = lse(wei) - wei[d]
        float w0 = wei[lane], w1 = wei[lane + 32];
        float mx = fmaxf(w0, w1);
        #pragma unroll
        for (int o = 16; o; o >>= 1) mx = fmaxf(mx, __shfl_xor_sync(0xffffffffu, mx, o));
        float s = __expf(w0 - mx) + __expf(w1 - mx);
        #pragma unroll
        for (int o = 16; o; o >>= 1) s += __shfl_xor_sync(0xffffffffu, s, o);
        if (lane == 0) g_a[d] = mx + logf(s) - wei[d];
    }
}

// ======== k1: w[b][t][d] = exp(+sqrt(||x_t - dic_d||^2) * a[d]) ========
// grid (64, 8) = 512 CTAs x 256 thr = 4096 warps. Micro-tile 2t x 4d.
// ALL staging coalesced LDG; inner: 1 LDS.64(bcast) + 1 LDS.128(2ph) + 4 dup + 4 FFMA2.
struct __align__(16) Smem1 {
    float sxT[Fn][36];    // [k][t ^ 4*((k>>2)&7)], 18.4 KB (rows 144B: 16B-aligned)
    float sdT[Fn][68];    // [k][d] natural, 34.8 KB (rows 272B: 16B-aligned)
    float sxx[T1];        // ||x_t||^2
};
__global__ void __launch_bounds__(256) k1(const float* __restrict__ x) {
    extern __shared__ __align__(16) char smem_raw[];
    Smem1& sm = *(Smem1*)smem_raw;
    int b = blockIdx.y;
    int t_base = blockIdx.x * T1;
    int tid = threadIdx.x;
    int lane = tid & 31;
    int dgrp = tid & 15, tgrp = tid >> 4;   // 16 d-groups x 16 t-groups
    int d0 = dgrp * 4, t0 = tgrp * 2;

    // ---- stage x transposed (coalesced LDG; XOR-rotated cols -> 4-way STS) ----
    // idx = q*256+tid: t = idx>>5 = 8q + warp (lane-invariant!), f4 = lane-major.
    #pragma unroll
    for (int q = 0; q < 4; q++) {
        int idx = q * 256 + tid;
        int t = idx >> 5;                // 0..31, fixed per (q, warp)
        int f4 = idx & 31;               // k-quad = f4
        float4 v = *(const float4*)(x + (size_t)(b * Tn + t_base + t) * Fn + 4 * f4);
        int cx = t ^ (4 * (f4 & 7));     // same col for all 4 k of this quad
        sm.sxT[4 * f4 + 0][cx] = v.x;
        sm.sxT[4 * f4 + 1][cx] = v.y;
        sm.sxT[4 * f4 + 2][cx] = v.z;
        sm.sxT[4 * f4 + 3][cx] = v.w;
        // ||x_t||^2: whole warp shares t -> warp-reduce, exactly one (q,warp) per t
        float p = fmaf(v.x, v.x, fmaf(v.y, v.y, fmaf(v.z, v.z, v.w * v.w)));
        #pragma unroll
        for (int o = 16; o; o >>= 1) p += __shfl_xor_sync(0xffffffffu, p, o);
        if (lane == 0) sm.sxx[t] = p;
    }
    // ---- stage dic natural from pre-transposed g_dT (fully coalesced) ----
    #pragma unroll
    for (int q = 0; q < 8; q++) {
        int idx = q * 256 + tid;
        int kl = idx >> 4;               // 0..127
        int d4 = (idx & 15) * 4;
        *(float4*)&sm.sdT[kl][d4] = *(const float4*)(g_dT + (size_t)kl * Dn + d4);
    }
    __syncthreads();                     // single sync

    u64 acc0 = 0, acc1 = 0, acc2 = 0, acc3 = 0;   // (t0,t1) pairs for d0..d0+3
    #pragma unroll 1
    for (int m = 0; m < 4; m++) {        // blocks of 32 k: XOR pattern compile-time
        int kb = m * 32;
        #pragma unroll
        for (int j = 0; j < 32; j++) {
            int k = kb + j;
            int cx = t0 ^ (4 * ((j >> 2) & 7));        // (k>>2)&7 == (j>>2)&7 (kb%32==0)
            u64 tp = *(const u64*)&sm.sxT[k][cx];      // (x[t0][k], x[t0+1][k])
            float4 dv = *(const float4*)&sm.sdT[k][d0];
            u64 p0, p1, p2, p3;
            PACK2(p0, dv.x, dv.x); PACK2(p1, dv.y, dv.y);
            PACK2(p2, dv.z, dv.z); PACK2(p3, dv.w, dv.w);
            FFMA2(acc0, tp, p0, acc0);
            FFMA2(acc1, tp, p1, acc1);
            FFMA2(acc2, tp, p2, acc2);
            FFMA2(acc3, tp, p3, acc3);
        }
    }

    float xx0 = sm.sxx[t0], xx1 = sm.sxx[t0 + 1];
    float4 dd4 = *(const float4*)&g_dd[d0];
    float4 a4  = *(const float4*)&g_a[d0];
    float ddv[4] = {dd4.x, dd4.y, dd4.z, dd4.w};
    float av[4]  = {a4.x, a4.y, a4.z, a4.w};
    float lo[4], hi[4];
    UNPACK2(lo[0], hi[0], acc0); UNPACK2(lo[1], hi[1], acc1);
    UNPACK2(lo[2], hi[2], acc2); UNPACK2(lo[3], hi[3], acc3);

    float o0[4], o1[4];
    #pragma unroll
    for (int j = 0; j < 4; j++) {
        float d2a = fmaxf(xx0 + ddv[j] - 2.0f * lo[j], 0.0f);
        float d2b = fmaxf(xx1 + ddv[j] - 2.0f * hi[j], 0.0f);
        // logit = +dis*a in ~[42,71]; exp finite fp32 -> no max-subtraction pass
        o0[j] = __expf(sqrtf(d2a) * av[j]);
        o1[j] = __expf(sqrtf(d2b) * av[j]);
    }
    float* r0 = g_w + (size_t)(b * Tn + t_base + t0) * Dn + d0;
    *(float4*)r0            = make_float4(o0[0], o0[1], o0[2], o0[3]);
    *(float4*)(r0 + Dn)     = make_float4(o1[0], o1[1], o1[2], o1[3]);
}

// ======== k3: partial[b][ch][d][f] = sum_t w*x ; psum = sum_t w ========
// grid (64, 8) = 512 CTAs x 256 thr = 4096 warps. Micro-tile 4d x 8f, TC=32.
// Staging coalesced (proven pattern from R12-k3); inner 5 LDS.128 + 16 FFMA2, 0 packs.
struct __align__(16) Smem3 {
    float sxD[TC][2 * Fn];   // [t][2f] dup'd x, 32 KB
    float sw[TC][Dn + 4];    // [t][d] natural w, pad 68, 8.7 KB
};
__global__ void __launch_bounds__(256) k3(const float* __restrict__ x) {
    extern __shared__ __align__(16) char smem_raw[];
    Smem3& sm = *(Smem3*)smem_raw;
    int ch = blockIdx.x, b = blockIdx.y;
    int tid = threadIdx.x;
    int dgrp = tid & 15, fgrp = tid >> 4;   // 16 x 16
    int d0 = dgrp * 4, f0 = fgrp * 8;
    int t_base = ch * TC;

    // stage w natural (coalesced): 32t x 16 float4 = 512 -> q<2 exact coverage
    #pragma unroll
    for (int q = 0; q < 2; q++) {
        int idx = q * 256 + tid;
        int t = idx >> 4, d4 = (idx & 15) * 4;
        *(float4*)&sm.sw[t][d4] =
            *(const float4*)(g_w + (size_t)(b * Tn + t_base + t) * Dn + d4);
    }
    // stage x dup'd: lanes -> f consecutive (coalesced LDG.32, 2-phase STS.64)
    {
        int f = tid & 127, th = tid >> 7;   // th in {0,1}
        const float* xc = x + (size_t)(b * Tn + t_base + th) * Fn + f;
        #pragma unroll
        for (int q = 0; q < 16; q++) {      // t = 2q + th covers 0..31
            float v = xc[(size_t)(2 * q) * Fn];
            u64 p; PACK2(p, v, v);
            *(u64*)&sm.sxD[2 * q + th][2 * f] = p;
        }
    }
    __syncthreads();

    u64 acc[2][8];            // [d-pair][f]
    #pragma unroll
    for (int j = 0; j < 2; j++)
        #pragma unroll
        for (int f = 0; f < 8; f++) acc[j][f] = 0ULL;

    #pragma unroll 4
    for (int t = 0; t < TC; t++) {
        ulonglong2 wp = *(const ulonglong2*)&sm.sw[t][d0];          // (d0,d1),(d2,d3)
        ulonglong2 x0 = *(const ulonglong2*)&sm.sxD[t][2 * f0];     // dup f0, f1
        ulonglong2 x1 = *(const ulonglong2*)&sm.sxD[t][2 * f0 + 4]; // dup f2, f3
        ulonglong2 x2 = *(const ulonglong2*)&sm.sxD[t][2 * f0 + 8]; // dup f4, f5
        ulonglong2 x3 = *(const ulonglong2*)&sm.sxD[t][2 * f0 + 12];// dup f6, f7
        FFMA2(acc[0][0], wp.x, x0.x, acc[0][0]); FFMA2(acc[1][0], wp.y, x0.x, acc[1][0]);
        FFMA2(acc[0][1], wp.x, x0.y, acc[0][1]); FFMA2(acc[1][1], wp.y, x0.y, acc[1][1]);
        FFMA2(acc[0][2], wp.x, x1.x, acc[0][2]); FFMA2(acc[1][2], wp.y, x1.x, acc[1][2]);
        FFMA2(acc[0][3], wp.x, x1.y, acc[0][3]); FFMA2(acc[1][3], wp.y, x1.y, acc[1][3]);
        FFMA2(acc[0][4], wp.x, x2.x, acc[0][4]); FFMA2(acc[1][4], wp.y, x2.x, acc[1][4]);
        FFMA2(acc[0][5], wp.x, x2.y, acc[0][5]); FFMA2(acc[1][5], wp.y, x2.y, acc[1][5]);
        FFMA2(acc[0][6], wp.x, x3.x, acc[0][6]); FFMA2(acc[1][6], wp.y, x3.x, acc[1][6]);
        FFMA2(acc[0][7], wp.x, x3.y, acc[0][7]); FFMA2(acc[1][7], wp.y, x3.y, acc[1][7]);
    }

    if (tid < Dn) {           // per-chunk weight sums (pad-68 rows: conflict-free)
        float s = 0.f;
        #pragma unroll 8
        for (int t = 0; t < TC; t++) s += sm.sw[t][tid];
        g_psum[(b * NCH + ch) * Dn + tid] = s;
    }

    // acc[j][f] = (partial[d0+2j][f0+f], partial[d0+2j+1][f0+f])
    float* pp = g_partial + ((size_t)(b * NCH + ch) * Dn) * Fn;
    #pragma unroll
    for (int j = 0; j < 2; j++) {
        float lo[8], hi[8];
        #pragma unroll
        for (int f = 0; f < 8; f++) UNPACK2(lo[f], hi[f], acc[j][f]);
        float* r0 = pp + (size_t)(d0 + 2 * j) * Fn + f0;
        float* r1 = pp + (size_t)(d0 + 2 * j + 1) * Fn + f0;
        *(float4*)(r0)     = make_float4(lo[0], lo[1], lo[2], lo[3]);
        *(float4*)(r0 + 4) = make_float4(lo[4], lo[5], lo[6], lo[7]);
        *(float4*)(r1)     = make_float4(hi[0], hi[1], hi[2], hi[3]);
        *(float4*)(r1 + 4) = make_float4(hi[4], hi[5], hi[6], hi[7]);
    }
}

// ======== k4: out[b][d][f] = (sum_ch partial)/P - dic ========
// grid 512 = one block per (b,d), 256 thr: 8 groups x 8 chunks (MLP 8, L2-resident).
__global__ void __launch_bounds__(256) k4(const float* __restrict__ dic,
                                          float* __restrict__ out) {
    __shared__ float4 sp[8][32];
    __shared__ float sP;
    int bd = blockIdx.x;
    int b = bd >> 6, d = bd & 63;
    int tid = threadIdx.x;
    int f4 = tid & 31, grp = tid >> 5;

    if (tid < 32) {           // P = sum over 64 chunks
        float s = g_psum[(b * NCH + tid) * Dn + d]
                + g_psum[(b * NCH + tid + 32) * Dn + d];
        #pragma unroll
        for (int o = 16; o; o >>= 1) s += __shfl_xor_sync(0xffffffffu, s, o);
        if (tid == 0) sP = s;
    }

    const float4* p = (const float4*)g_partial
        + ((size_t)(b * NCH + grp * 8) * Dn + d) * (Fn / 4) + f4;
    float4 s = make_float4(0.f, 0.f, 0.f, 0.f);
    #pragma unroll
    for (int i = 0; i < 8; i++) {
        float4 v = p[(size_t)i * Dn * (Fn / 4)];
        s.x += v.x; s.y += v.y; s.z += v.z; s.w += v.w;
    }
    sp[grp][f4] = s;
    __syncthreads();

    if (tid < 32) {
        float4 r = make_float4(0.f, 0.f, 0.f, 0.f);
        #pragma unroll
        for (int g = 0; g < 8; g++) {
            float4 v = sp[g][f4];
            r.x += v.x; r.y += v.y; r.z += v.z; r.w += v.w;
        }
        float inv = 1.0f / sP;
        float4 dc = ((const float4*)dic)[d * (Fn / 4) + f4];
        ((float4*)out)[bd * (Fn / 4) + f4] =
            make_float4(r.x * inv - dc.x, r.y * inv - dc.y,
                        r.z * inv - dc.z, r.w * inv - dc.w);
    }
}

// ---------------- launch ----------------
extern "C" void kernel_launch(void* const* d_in, const int* in_sizes, int n_in,
                              void* d_out, int out_size) {
    const float* x = 0; const float* dic = 0; const float* wei = 0;
    for (int i = 0; i < n_in; i++) {
        if (in_sizes[i] == Bn * Tn * Fn)      x   = (const float*)d_in[i];
        else if (in_sizes[i] == Dn * Fn)      dic = (const float*)d_in[i];
        else if (in_sizes[i] == Dn)           wei = (const float*)d_in[i];
    }
    float* out = (float*)d_out;

    int s1 = (int)sizeof(Smem1);   // ~53.4 KB -> 4 CTAs/SM
    int s3 = (int)sizeof(Smem3);   // ~41.5 KB -> 5 CTAs/SM
    cudaFuncSetAttribute(k1, cudaFuncAttributeMaxDynamicSharedMemorySize, s1);
    cudaFuncSetAttribute(k3, cudaFuncAttributeMaxDynamicSharedMemorySize, s3);

    k0<<<Dn, 128>>>(dic, wei);
    k1<<<dim3(Tn / T1, Bn), 256, s1>>>(x);
    k3<<<dim3(NCH, Bn), 256, s3>>>(x);
    k4<<<Bn * Dn, 256>>>(dic, out);
}

// round 14
// speedup vs baseline: 1.8374x; 1.8374x over previous
#include <cuda_runtime.h>
#include <math.h>

#define Bn 8
#define Tn 2048
#define Dn 64
#define Fn 128
#define NCH 32      // T-chunks in k3 / partial
#define TC 64       // T per k3 chunk
#define KC 32       // K chunk in k1

// ---------------- scratch (static device globals: allocation-free) ----------------
__device__ float g_w[(size_t)Bn * Tn * Dn];             // [b][t][d], 4 MB
__device__ float g_psum[Bn * NCH * Dn];                 // per-chunk sum_t w
__device__ float g_partial[(size_t)Bn * NCH * Dn * Fn]; // [b][ch][d][f], 8 MB

typedef unsigned long long u64;
#define PACK2(dst, lo, hi)   asm("mov.b64 %0, {%1, %2};" : "=l"(dst) : "f"(lo), "f"(hi))
#define UNPACK2(lo, hi, src) asm("mov.b64 {%0, %1}, %2;" : "=f"(lo), "=f"(hi) : "l"(src))
#define FFMA2(d_, a_, b_, c_) asm("fma.rn.f32x2 %0, %1, %2, %3;" : "=l"(d_) : "l"(a_), "l"(b_), "l"(c_))

// -------- k1: w[b][t][d] = exp(+sqrt(||x_t - dic_d||^2) * a[d])  (logit POSITIVE) --
// EXACT structure of the measured-18.8us kernel (R5), with ||x||^2 and ||dic||^2
// hoisted OUT of the inner loop (computed from the same staging loads via 8-lane
// shfl reduces). Inner loop: 2 LDS + 4 PACK + 8 FFMA2 (was 20 instr -> 14).
__global__ void __launch_bounds__(128) k1(const float* __restrict__ x,
                                          const float* __restrict__ dic,
                                          const float* __restrict__ wei) {
    __shared__ float sxT[KC][36];   // [k][t], pad->36
    __shared__ float sdT[KC][68];   // [k][d]
    __shared__ __align__(16) float sa[Dn];
    __shared__ __align__(16) float sdd[Dn];
    __shared__ float sxx[32];
    int b = blockIdx.y;
    int t_base = blockIdx.x * 32;
    int tid = threadIdx.x;
    int d0 = (tid & 15) * 4;
    int t0 = (tid >> 4) * 4;

    // warp 0: a[d] = lse(wei) - wei[d]  (before first sync)
    if (tid < 32) {
        float w0 = wei[tid], w1 = wei[tid + 32];
        float mx = fmaxf(w0, w1);
        #pragma unroll
        for (int o = 16; o; o >>= 1) mx = fmaxf(mx, __shfl_xor_sync(0xffffffffu, mx, o));
        float s = __expf(w0 - mx) + __expf(w1 - mx);
        #pragma unroll
        for (int o = 16; o; o >>= 1) s += __shfl_xor_sync(0xffffffffu, s, o);
        float lse = mx + logf(s);
        sa[tid]      = lse - w0;
        sa[tid + 32] = lse - w1;
    }

    u64 acc[2][4];                  // [t-pair][d]
    #pragma unroll
    for (int p = 0; p < 2; p++)
        #pragma unroll
        for (int j = 0; j < 4; j++) acc[p][j] = 0ULL;

    float pxx[2] = {0.f, 0.f};      // ||x_t||^2 partials (rows 16q + tid>>3)
    float pdd[4] = {0.f, 0.f, 0.f, 0.f};  // ||dic_d||^2 partials

    const float* xb = x + (size_t)(b * Tn + t_base) * Fn;

    for (int kc = 0; kc < Fn / KC; kc++) {
        // stage x 32t x 32k transposed: 256 float4, 2 per thread (+ xx accumulation)
        #pragma unroll
        for (int q = 0; q < 2; q++) {
            int qi = q * 128 + tid;
            int r = qi >> 3;                 // t row = 16q + tid>>3 (fixed across kc)
            int k = (qi & 7) * 4;
            float4 v = *(const float4*)(xb + (size_t)r * Fn + kc * KC + k);
            pxx[q] = fmaf(v.x, v.x, fmaf(v.y, v.y, fmaf(v.z, v.z, fmaf(v.w, v.w, pxx[q]))));
            sxT[k + 0][r] = v.x; sxT[k + 1][r] = v.y;
            sxT[k + 2][r] = v.z; sxT[k + 3][r] = v.w;
        }
        // stage dic 64d x 32k transposed (+ dd accumulation)
        #pragma unroll
        for (int q = 0; q < 4; q++) {
            int qi = q * 128 + tid;
            int dr = qi >> 3;                // d row = 16q + tid>>3 (fixed across kc)
            int kk = (qi & 7) * 4;
            float4 v = *(const float4*)(dic + (size_t)dr * Fn + kc * KC + kk);
            pdd[q] = fmaf(v.x, v.x, fmaf(v.y, v.y, fmaf(v.z, v.z, fmaf(v.w, v.w, pdd[q]))));
            sdT[kk + 0][dr] = v.x; sdT[kk + 1][dr] = v.y;
            sdT[kk + 2][dr] = v.z; sdT[kk + 3][dr] = v.w;
        }
        if (kc == Fn / KC - 1) {
            // 8-lane-group reduces (rows owned by aligned groups of 8 lanes)
            #pragma unroll
            for (int q = 0; q < 2; q++) {
                float p = pxx[q];
                p += __shfl_xor_sync(0xffffffffu, p, 1);
                p += __shfl_xor_sync(0xffffffffu, p, 2);
                p += __shfl_xor_sync(0xffffffffu, p, 4);
                if ((tid & 7) == 0) sxx[16 * q + (tid >> 3)] = p;
            }
            #pragma unroll
            for (int q = 0; q < 4; q++) {
                float p = pdd[q];
                p += __shfl_xor_sync(0xffffffffu, p, 1);
                p += __shfl_xor_sync(0xffffffffu, p, 2);
                p += __shfl_xor_sync(0xffffffffu, p, 4);
                if ((tid & 7) == 0) sdd[16 * q + (tid >> 3)] = p;
            }
        }
        __syncthreads();
        #pragma unroll 8
        for (int k = 0; k < KC; k++) {
            ulonglong2 tp = *(ulonglong2*)&sxT[k][t0];   // free f32x2 t-pairs
            float4 dv = *(float4*)&sdT[k][d0];
            u64 ds[4];
            PACK2(ds[0], dv.x, dv.x); PACK2(ds[1], dv.y, dv.y);
            PACK2(ds[2], dv.z, dv.z); PACK2(ds[3], dv.w, dv.w);
            #pragma unroll
            for (int j = 0; j < 4; j++) {
                FFMA2(acc[0][j], tp.x, ds[j], acc[0][j]);
                FFMA2(acc[1][j], tp.y, ds[j], acc[1][j]);
            }
        }
        __syncthreads();
    }

    float xxv[4];
    xxv[0] = sxx[t0]; xxv[1] = sxx[t0 + 1];
    xxv[2] = sxx[t0 + 2]; xxv[3] = sxx[t0 + 3];
    float4 dd4 = *(float4*)&sdd[d0];
    float4 a4  = *(float4*)&sa[d0];
    float ddv[4] = {dd4.x, dd4.y, dd4.z, dd4.w};
    float av[4]  = {a4.x, a4.y, a4.z, a4.w};

    #pragma unroll
    for (int i = 0; i < 4; i++) {           // t row
        float o[4];
        #pragma unroll
        for (int j = 0; j < 4; j++) {
            float lo, hi;
            UNPACK2(lo, hi, acc[i >> 1][j]);
            float dot = (i & 1) ? hi : lo;
            float d2 = fmaxf(xxv[i] + ddv[j] - 2.0f * dot, 0.0f);
            // logit = +dis * a, range ~[42, 71]: exp finite fp32, no max pass needed
            o[j] = __expf(sqrtf(d2) * av[j]);
        }
        float* row = g_w + (size_t)(b * Tn + t_base + t0 + i) * Dn + d0;
        *(float4*)row = make_float4(o[0], o[1], o[2], o[3]);
    }
}

// ======== k3: partial[b][ch][d][f_half] = sum_t w*x ; psum = sum_t w ========
// grid (NCH*2, 8) = 512 CTAs x 256 thr = 4096 warps; each CTA does 64d x 64f (one
// f-half) over TC=64 t. Micro-tile 4d x 4f. Staging fully coalesced.
__global__ void __launch_bounds__(256) k3(const float* __restrict__ x) {
    __shared__ float sx[TC][64];    // [t][f-local] (row 64: xa reads are broadcast)
    __shared__ float sw[TC][Dn + 4];// [t][d], pad 68
    int bx = blockIdx.x, b = blockIdx.y;
    int ch = bx >> 1, fh = bx & 1;
    int f_base = fh * 64;
    int tid = threadIdx.x;
    int dgrp = tid & 15, fgrp = tid >> 4;   // 16 x 16
    int d0 = dgrp * 4, f0l = fgrp * 4;
    int t_base = ch * TC;

    // stage w (64t x 64d = 1024 float4, coalesced)
    #pragma unroll
    for (int q = 0; q < 4; q++) {
        int idx = q * 256 + tid;
        int t = idx >> 4, d4 = (idx & 15) * 4;
        *(float4*)&sw[t][d4] =
            *(const float4*)(g_w + (size_t)(b * Tn + t_base + t) * Dn + d4);
    }
    // stage x half-tile (64t x 64f = 1024 float4, coalesced)
    #pragma unroll
    for (int q = 0; q < 4; q++) {
        int idx = q * 256 + tid;
        int t = idx >> 4, c = (idx & 15) * 4;
        *(float4*)&sx[t][c] =
            *(const float4*)(x + (size_t)(b * Tn + t_base + t) * Fn + f_base + c);
    }
    __syncthreads();

    u64 acc[4][2];                  // [d][f-pair]
    #pragma unroll
    for (int i = 0; i < 4; i++) acc[i][0] = acc[i][1] = 0ULL;

    #pragma unroll 8
    for (int t = 0; t < TC; t++) {
        float4 pv = *(float4*)&sw[t][d0];                 // 2-phase LDS.128
        ulonglong2 xa = *(ulonglong2*)&sx[t][f0l];        // broadcast (2 addrs/warp)
        u64 p0, p1, p2, p3;
        PACK2(p0, pv.x, pv.x); PACK2(p1, pv.y, pv.y);
        PACK2(p2, pv.z, pv.z); PACK2(p3, pv.w, pv.w);
        FFMA2(acc[0][0], p0, xa.x, acc[0][0]); FFMA2(acc[0][1], p0, xa.y, acc[0][1]);
        FFMA2(acc[1][0], p1, xa.x, acc[1][0]); FFMA2(acc[1][1], p1, xa.y, acc[1][1]);
        FFMA2(acc[2][0], p2, xa.x, acc[2][0]); FFMA2(acc[2][1], p2, xa.y, acc[2][1]);
        FFMA2(acc[3][0], p3, xa.x, acc[3][0]); FFMA2(acc[3][1], p3, xa.y, acc[3][1]);
    }

    // per-chunk weight sums; both f-halves compute identical values (benign dup write)
    if (tid < Dn) {
        float s = 0.f;
        #pragma unroll 8
        for (int t = 0; t < TC; t++) s += sw[t][tid];
        g_psum[(b * NCH + ch) * Dn + tid] = s;
    }

    float* pp = g_partial + ((size_t)(b * NCH + ch) * Dn) * Fn;
    #pragma unroll
    for (int i = 0; i < 4; i++) {
        float o[4];
        UNPACK2(o[0], o[1], acc[i][0]);
        UNPACK2(o[2], o[3], acc[i][1]);
        *(float4*)(pp + (size_t)(d0 + i) * Fn + f_base + f0l) =
            make_float4(o[0], o[1], o[2], o[3]);
    }
}

// ======== k4: out[b][d][f] = (sum_ch partial)/P - dic ========
// grid 512 = one block per (b,d), 128 thr, 4 groups x 8 chunks (L2-resident).
__global__ void __launch_bounds__(128) k4(const float* __restrict__ dic,
                                          float* __restrict__ out) {
    __shared__ float4 sp[4][32];
    __shared__ float sP;
    int bd = blockIdx.x;
    int b = bd >> 6, d = bd & 63;
    int tid = threadIdx.x;
    int f4 = tid & 31, grp = tid >> 5;

    if (tid < 32) {           // P = sum_ch psum (32 chunks)
        float s = g_psum[(b * NCH + tid) * Dn + d];
        #pragma unroll
        for (int o = 16; o; o >>= 1) s += __shfl_xor_sync(0xffffffffu, s, o);
        if (tid == 0) sP = s;
    }

    const float4* p = (const float4*)g_partial
        + ((size_t)(b * NCH + grp * 8) * Dn + d) * (Fn / 4) + f4;
    float4 s = make_float4(0.f, 0.f, 0.f, 0.f);
    #pragma unroll
    for (int i = 0; i < 8; i++) {
        float4 v = p[(size_t)i * Dn * (Fn / 4)];
        s.x += v.x; s.y += v.y; s.z += v.z; s.w += v.w;
    }
    sp[grp][f4] = s;
    __syncthreads();

    if (tid < 32) {
        float4 a = sp[0][f4], b4 = sp[1][f4], c = sp[2][f4], e = sp[3][f4];
        float inv = 1.0f / sP;
        float4 dc = ((const float4*)dic)[d * (Fn / 4) + f4];
        ((float4*)out)[bd * (Fn / 4) + f4] =
            make_float4((a.x + b4.x + c.x + e.x) * inv - dc.x,
                        (a.y + b4.y + c.y + e.y) * inv - dc.y,
                        (a.z + b4.z + c.z + e.z) * inv - dc.z,
                        (a.w + b4.w + c.w + e.w) * inv - dc.w);
    }
}

// ---------------- launch ----------------
extern "C" void kernel_launch(void* const* d_in, const int* in_sizes, int n_in,
                              void* d_out, int out_size) {
    const float* x = 0; const float* dic = 0; const float* wei = 0;
    for (int i = 0; i < n_in; i++) {
        if (in_sizes[i] == Bn * Tn * Fn)      x   = (const float*)d_in[i];
        else if (in_sizes[i] == Dn * Fn)      dic = (const float*)d_in[i];
        else if (in_sizes[i] == Dn)           wei = (const float*)d_in[i];
    }
    float* out = (float*)d_out;

    k1<<<dim3(Tn / 32, Bn), 128>>>(x, dic, wei);
    k3<<<dim3(NCH * 2, Bn), 256>>>(x);
    k4<<<Bn * Dn, 128>>>(dic, out);
}